// round 4
// baseline (speedup 1.0000x reference)
#include <cuda_runtime.h>
#include <float.h>
#include <stdint.h>

#define Bb 2
#define Ss 2048
#define Dd 768
#define Hh 12
#define DH 64
#define Mm (Bb*Ss)

// ---------------- scratch ----------------
__device__ float g_Q[(size_t)Bb*Hh*Ss*DH];
__device__ float g_K[(size_t)Bb*Hh*Ss*DH];
__device__ float g_V[(size_t)Bb*Hh*Ss*DH];
__device__ float g_O[(size_t)Mm*Dd];

// ---------------- helpers ----------------
__device__ __forceinline__ uint32_t smem_u32(const void* p) {
    uint32_t a;
    asm("{ .reg .u64 t; cvta.to.shared.u64 t, %1; cvt.u32.u64 %0, t; }" : "=r"(a) : "l"(p));
    return a;
}
__device__ __forceinline__ void cp16(uint32_t dst, const float* src) {
    asm volatile("cp.async.cg.shared.global [%0], [%1], 16;"
        :: "r"(dst), "l"(__cvta_generic_to_global(src)));
}
__device__ __forceinline__ void cp_commit() { asm volatile("cp.async.commit_group;"); }
__device__ __forceinline__ void cp_wait0()  { asm volatile("cp.async.wait_group 0;"); }
__device__ __forceinline__ void cp_wait1()  { asm volatile("cp.async.wait_group 1;"); }
__device__ __forceinline__ void cp_wait2()  { asm volatile("cp.async.wait_group 2;"); }

__device__ __forceinline__ float to_tf32(float x) {
    uint32_t u;
    asm("cvt.rna.tf32.f32 %0, %1;" : "=r"(u) : "f"(x));
    return __uint_as_float(u);
}
// 3xtf32 decomposition: x ~= hi + lo, both tf32-representable
__device__ __forceinline__ void dec(float x, uint32_t& hi, uint32_t& lo) {
    asm("cvt.rna.tf32.f32 %0, %1;" : "=r"(hi) : "f"(x));
    float r = x - __uint_as_float(hi);
    asm("cvt.rna.tf32.f32 %0, %1;" : "=r"(lo) : "f"(r));
}
__device__ __forceinline__ void mma8(float* d, const uint32_t* a, const uint32_t* b) {
    asm volatile("mma.sync.aligned.m16n8k8.row.col.f32.tf32.tf32.f32 "
        "{%0,%1,%2,%3}, {%4,%5,%6,%7}, {%8,%9}, {%0,%1,%2,%3};"
        : "+f"(d[0]), "+f"(d[1]), "+f"(d[2]), "+f"(d[3])
        : "r"(a[0]), "r"(a[1]), "r"(a[2]), "r"(a[3]), "r"(b[0]), "r"(b[1]));
}
__device__ __forceinline__ uint32_t f2u(float x) { return __float_as_uint(x); }

// ---------------- 3xtf32 GEMM core ----------------
// CTA 128x128, BK=16, 256 threads (8 warps: wm=wid>>1 in 0..3, wn=wid&1).
// Warp tile 32x64 (2 mtiles x 8 ntiles). A[M,768], B[N,768] K-major raw fp32.
#define GSTG 5120
#define GCH  48

__device__ __forceinline__ void gemm_core3(const float* __restrict__ Arow,
                                           const float* __restrict__ Brow,
                                           float* sm, float acc[2][8][4]) {
    const int tid = threadIdx.x;
    const int lane = tid & 31;
    const int wid = tid >> 5;
    const int wm = wid >> 1, wn = wid & 1;

    uint32_t sA = smem_u32(sm);
    uint32_t sB = sA + 2560u * 4u;

    #pragma unroll
    for (int mt = 0; mt < 2; mt++)
        #pragma unroll
        for (int nt = 0; nt < 8; nt++)
            #pragma unroll
            for (int q = 0; q < 4; q++) acc[mt][nt][q] = 0.f;

    const int lr = tid >> 2;            // 0..63 -> covers 128 rows in 2 steps? no:
    // load map: idx = t*256+tid, t=0..1 per array; r=idx>>2 (0..127), e=(idx&3)*4
    #pragma unroll
    for (int c = 0; c < 3; c++) {
        #pragma unroll
        for (int t = 0; t < 2; t++) {
            int idx = t * 256 + tid;
            int r = idx >> 2, e = (idx & 3) << 2;
            cp16(sA + (c * GSTG + r * 20 + e) * 4, Arow + (size_t)r * Dd + c * 16 + e);
            cp16(sB + (c * GSTG + r * 20 + e) * 4, Brow + (size_t)r * Dd + c * 16 + e);
        }
        cp_commit();
    }
    (void)lr;

    const int cL = lane & 3, rL = lane >> 2;

    for (int c = 0; c < GCH; c++) {
        cp_wait2();
        __syncthreads();
        if (c + 3 < GCH) {
            int st = (c + 3) & 3;
            #pragma unroll
            for (int t = 0; t < 2; t++) {
                int idx = t * 256 + tid;
                int r = idx >> 2, e = (idx & 3) << 2;
                cp16(sA + (st * GSTG + r * 20 + e) * 4, Arow + (size_t)r * Dd + (c + 3) * 16 + e);
                cp16(sB + (st * GSTG + r * 20 + e) * 4, Brow + (size_t)r * Dd + (c + 3) * 16 + e);
            }
        }
        cp_commit();

        const float* As = sm + (c & 3) * GSTG;
        const float* Bs = As + 2560;
        #pragma unroll
        for (int ks = 0; ks < 2; ks++) {
            const int kb = ks * 8 + cL;
            uint32_t ah[2][4], al[2][4];
            #pragma unroll
            for (int mt = 0; mt < 2; mt++) {
                const float* ap = As + (wm * 32 + mt * 16 + rL) * 20;
                dec(ap[kb],           ah[mt][0], al[mt][0]);
                dec(ap[8 * 20 + kb],  ah[mt][1], al[mt][1]);
                dec(ap[kb + 4],       ah[mt][2], al[mt][2]);
                dec(ap[8 * 20 + kb + 4], ah[mt][3], al[mt][3]);
            }
            #pragma unroll
            for (int nt = 0; nt < 8; nt++) {
                const float* bp = Bs + (wn * 64 + nt * 8 + rL) * 20;
                uint32_t bh[2], bl[2];
                dec(bp[kb],     bh[0], bl[0]);
                dec(bp[kb + 4], bh[1], bl[1]);
                #pragma unroll
                for (int mt = 0; mt < 2; mt++) {
                    mma8(acc[mt][nt], al[mt], bh);
                    mma8(acc[mt][nt], ah[mt], bl);
                    mma8(acc[mt][nt], ah[mt], bh);
                }
            }
        }
    }
}

// QKV projection (3xtf32): epilogue rounds to tf32, scales Q, scatters to [B,H,S,DH]
__global__ __launch_bounds__(256, 2) void gemm_qkv_tc(
    const float* __restrict__ X, const float* __restrict__ Wq,
    const float* __restrict__ Wk, const float* __restrict__ Wv)
{
    extern __shared__ float sm[];
    const int z = blockIdx.z;
    const float* W = (z == 0) ? Wq : (z == 1 ? Wk : Wv);
    float* Obuf = (z == 0) ? g_Q : (z == 1 ? g_K : g_V);
    const float scale = (z == 0) ? 0.125f : 1.0f;
    const int mBase = blockIdx.x * 128, nBase = blockIdx.y * 128;

    float acc[2][8][4];
    gemm_core3(X + (size_t)mBase * Dd, W + (size_t)nBase * Dd, sm, acc);

    const int lane = threadIdx.x & 31, wid = threadIdx.x >> 5;
    const int wm = wid >> 1, wn = wid & 1;
    const int h = (nBase + wn * 64) >> 6;
    #pragma unroll
    for (int mt = 0; mt < 2; mt++) {
        int r0 = mBase + wm * 32 + mt * 16 + (lane >> 2);
        #pragma unroll
        for (int half = 0; half < 2; half++) {
            int row = r0 + half * 8;
            int bb = row >> 11, ssi = row & 2047;
            float* dst = Obuf + (((size_t)bb * Hh + h) * Ss + ssi) * DH;
            #pragma unroll
            for (int nt = 0; nt < 8; nt++) {
                int d = nt * 8 + 2 * (lane & 3);
                *(float2*)(dst + d) = make_float2(
                    to_tf32(acc[mt][nt][half * 2 + 0] * scale),
                    to_tf32(acc[mt][nt][half * 2 + 1] * scale));
            }
        }
    }
}

// output projection (3xtf32): plain fp32 store
__global__ __launch_bounds__(256, 2) void gemm_out_tc(
    const float* __restrict__ Wo, float* __restrict__ C)
{
    extern __shared__ float sm[];
    const int mBase = blockIdx.x * 128, nBase = blockIdx.y * 128;

    float acc[2][8][4];
    gemm_core3(g_O + (size_t)mBase * Dd, Wo + (size_t)nBase * Dd, sm, acc);

    const int lane = threadIdx.x & 31, wid = threadIdx.x >> 5;
    const int wm = wid >> 1, wn = wid & 1;
    #pragma unroll
    for (int mt = 0; mt < 2; mt++) {
        int r0 = mBase + wm * 32 + mt * 16 + (lane >> 2);
        #pragma unroll
        for (int half = 0; half < 2; half++) {
            int row = r0 + half * 8;
            float* dst = C + (size_t)row * Dd + nBase + wn * 64;
            #pragma unroll
            for (int nt = 0; nt < 8; nt++) {
                int d = nt * 8 + 2 * (lane & 3);
                *(float2*)(dst + d) = make_float2(acc[mt][nt][half * 2 + 0],
                                                  acc[mt][nt][half * 2 + 1]);
            }
        }
    }
}

// ---------------- flash attention, 256 threads, 8 warps x 16 rows ----------------
// smem floats: Qs[128][68] | Ks 3x[64][68] | Vs 3x[64][72] | Ps[128][72]
#define AQ 0
#define AK 8704
#define AV 21760
#define AP 35584
#define ATTN_FLOATS 44800

__global__ __launch_bounds__(256, 1) void attn_mma() {
    extern __shared__ float sm[];
    float* Qs = sm + AQ;
    float* Ps = sm + AP;

    const int tid = threadIdx.x;
    const int lane = tid & 31, wid = tid >> 5;
    const int qt = gridDim.x - 1 - blockIdx.x;   // heavy tiles first
    const int h = blockIdx.y, b = blockIdx.z;

    const float* Qg = g_Q + (((size_t)b * Hh + h) * Ss + (size_t)qt * 128) * DH;
    const float* Kg = g_K + (((size_t)b * Hh + h) * Ss) * DH;
    const float* Vg = g_V + (((size_t)b * Hh + h) * Ss) * DH;

    uint32_t sQ = smem_u32(sm) + AQ * 4;
    uint32_t sK = smem_u32(sm) + AK * 4;
    uint32_t sV = smem_u32(sm) + AV * 4;

    // Q tile load (group 0 together with KV0)
    #pragma unroll
    for (int t = 0; t < 8; t++) {
        int idx = t * 256 + tid;
        int r = idx >> 4, c4 = (idx & 15) << 2;
        cp16(sQ + (r * 68 + c4) * 4, Qg + r * DH + c4);
    }
    // KV tile 0 -> stage 0
    {
        const float* Kp = Kg; const float* Vp = Vg;
        #pragma unroll
        for (int t = 0; t < 4; t++) {
            int idx = t * 256 + tid;
            int r = idx >> 4, c4 = (idx & 15) << 2;
            cp16(sK + (0 * 4352 + r * 68 + c4) * 4, Kp + r * DH + c4);
            cp16(sV + (0 * 4608 + r * 72 + c4) * 4, Vp + r * DH + c4);
        }
    }
    cp_commit();

    float o[8][4];
    float mrow[2], lrow[2];
    mrow[0] = mrow[1] = -1e30f;
    lrow[0] = lrow[1] = 0.f;
    #pragma unroll
    for (int nt = 0; nt < 8; nt++)
        #pragma unroll
        for (int q = 0; q < 4; q++) o[nt][q] = 0.f;

    const int cL = lane & 3, rL = lane >> 2;
    const int ktMax = 2 * qt + 1;

    for (int kt = 0; kt <= ktMax; kt++) {
        // depth-1 prefetch of KV(kt+1) into stage (kt+1)%3
        bool pf = (kt + 1 <= ktMax);
        if (pf) {
            int st = (kt + 1) % 3;
            const float* Kp = Kg + (size_t)(kt + 1) * 64 * DH;
            const float* Vp = Vg + (size_t)(kt + 1) * 64 * DH;
            #pragma unroll
            for (int t = 0; t < 4; t++) {
                int idx = t * 256 + tid;
                int r = idx >> 4, c4 = (idx & 15) << 2;
                cp16(sK + (st * 4352 + r * 68 + c4) * 4, Kp + r * DH + c4);
                cp16(sV + (st * 4608 + r * 72 + c4) * 4, Vp + r * DH + c4);
            }
            cp_commit();
            cp_wait1();
        } else {
            cp_wait0();
        }
        __syncthreads();

        const float* Ks = sm + AK + (kt % 3) * 4352;
        const float* Vs = sm + AV + (kt % 3) * 4608;

        // S = Q K^T, warp rows wid*16..+15
        float s[8][4];
        #pragma unroll
        for (int nt = 0; nt < 8; nt++)
            #pragma unroll
            for (int q = 0; q < 4; q++) s[nt][q] = 0.f;

        const float* qp = Qs + (wid * 16 + rL) * 68;
        #pragma unroll
        for (int ks = 0; ks < 8; ks++) {
            const int kb = ks * 8 + cL;
            uint32_t a[4];
            a[0] = f2u(qp[kb]);
            a[1] = f2u(qp[8 * 68 + kb]);
            a[2] = f2u(qp[kb + 4]);
            a[3] = f2u(qp[8 * 68 + kb + 4]);
            #pragma unroll
            for (int nt = 0; nt < 8; nt++) {
                const float* kp = Ks + (nt * 8 + rL) * 68;
                uint32_t bfr[2] = { f2u(kp[kb]), f2u(kp[kb + 4]) };
                mma8(s[nt], a, bfr);
            }
        }

        // causal mask
        if (kt >= 2 * qt) {
            int rg0 = qt * 128 + wid * 16 + rL;
            #pragma unroll
            for (int nt = 0; nt < 8; nt++) {
                int cg = kt * 64 + nt * 8 + 2 * cL;
                if (cg     > rg0)     s[nt][0] = -1e30f;
                if (cg + 1 > rg0)     s[nt][1] = -1e30f;
                if (cg     > rg0 + 8) s[nt][2] = -1e30f;
                if (cg + 1 > rg0 + 8) s[nt][3] = -1e30f;
            }
        }

        // online softmax (rows rL, rL+8 of this warp's 16)
        float v0 = -1e30f, v1 = -1e30f;
        #pragma unroll
        for (int nt = 0; nt < 8; nt++) {
            v0 = fmaxf(v0, fmaxf(s[nt][0], s[nt][1]));
            v1 = fmaxf(v1, fmaxf(s[nt][2], s[nt][3]));
        }
        v0 = fmaxf(v0, __shfl_xor_sync(0xffffffffu, v0, 1));
        v0 = fmaxf(v0, __shfl_xor_sync(0xffffffffu, v0, 2));
        v1 = fmaxf(v1, __shfl_xor_sync(0xffffffffu, v1, 1));
        v1 = fmaxf(v1, __shfl_xor_sync(0xffffffffu, v1, 2));

        float mn0 = fmaxf(mrow[0], v0);
        float mn1 = fmaxf(mrow[1], v1);
        float cr0 = __expf(mrow[0] - mn0);
        float cr1 = __expf(mrow[1] - mn1);
        mrow[0] = mn0; mrow[1] = mn1;

        float rs0 = 0.f, rs1 = 0.f;
        float* prow0 = Ps + (wid * 16 + rL) * 72;
        float* prow1 = prow0 + 8 * 72;
        #pragma unroll
        for (int nt = 0; nt < 8; nt++) {
            float p0 = __expf(s[nt][0] - mn0);
            float p1 = __expf(s[nt][1] - mn0);
            float p2 = __expf(s[nt][2] - mn1);
            float p3 = __expf(s[nt][3] - mn1);
            rs0 += p0 + p1; rs1 += p2 + p3;
            int cc = nt * 8 + 2 * cL;
            *(float2*)(prow0 + cc) = make_float2(to_tf32(p0), to_tf32(p1));
            *(float2*)(prow1 + cc) = make_float2(to_tf32(p2), to_tf32(p3));
        }
        rs0 += __shfl_xor_sync(0xffffffffu, rs0, 1);
        rs0 += __shfl_xor_sync(0xffffffffu, rs0, 2);
        rs1 += __shfl_xor_sync(0xffffffffu, rs1, 1);
        rs1 += __shfl_xor_sync(0xffffffffu, rs1, 2);
        lrow[0] = lrow[0] * cr0 + rs0;
        lrow[1] = lrow[1] * cr1 + rs1;
        #pragma unroll
        for (int nt = 0; nt < 8; nt++) {
            o[nt][0] *= cr0; o[nt][1] *= cr0;
            o[nt][2] *= cr1; o[nt][3] *= cr1;
        }
        __syncthreads();   // Ps visible to own warp only, but Vs stage protection

        // O += P V
        const float* pp = Ps + (wid * 16 + rL) * 72;
        #pragma unroll
        for (int ks = 0; ks < 8; ks++) {
            const int kb = ks * 8;
            uint32_t a[4];
            a[0] = f2u(pp[kb + cL]);
            a[1] = f2u(pp[8 * 72 + kb + cL]);
            a[2] = f2u(pp[kb + 4 + cL]);
            a[3] = f2u(pp[8 * 72 + kb + 4 + cL]);
            #pragma unroll
            for (int nt = 0; nt < 8; nt++) {
                uint32_t bfr[2] = { f2u(Vs[(kb + cL) * 72 + nt * 8 + rL]),
                                    f2u(Vs[(kb + 4 + cL) * 72 + nt * 8 + rL]) };
                mma8(o[nt], a, bfr);
            }
        }
    }

    // epilogue: normalize, store raw fp32 (out-proj does 3xtf32 decomposition)
    float inv0 = 1.f / lrow[0];
    float inv1 = 1.f / lrow[1];
    int r0 = qt * 128 + wid * 16 + rL;
    float* d0 = g_O + ((size_t)b * Ss + r0) * Dd + h * DH;
    float* d1 = d0 + 8 * Dd;
    #pragma unroll
    for (int nt = 0; nt < 8; nt++) {
        int cc = nt * 8 + 2 * cL;
        *(float2*)(d0 + cc) = make_float2(o[nt][0] * inv0, o[nt][1] * inv0);
        *(float2*)(d1 + cc) = make_float2(o[nt][2] * inv1, o[nt][3] * inv1);
    }
}

// ---------------------------------------------------------------------------

extern "C" void kernel_launch(void* const* d_in, const int* in_sizes, int n_in,
                              void* d_out, int out_size)
{
    const float* x  = (const float*)d_in[0];
    const float* Wq = (const float*)d_in[1];
    const float* Wk = (const float*)d_in[2];
    const float* Wv = (const float*)d_in[3];
    const float* Wo = (const float*)d_in[4];
    float* out = (float*)d_out;

    const int GEMM_SMEM = 4 * GSTG * (int)sizeof(float);        // 81920
    const int ATTN_SMEM = ATTN_FLOATS * (int)sizeof(float);     // 179200

    cudaFuncSetAttribute(gemm_qkv_tc, cudaFuncAttributeMaxDynamicSharedMemorySize, GEMM_SMEM);
    cudaFuncSetAttribute(gemm_out_tc, cudaFuncAttributeMaxDynamicSharedMemorySize, GEMM_SMEM);
    cudaFuncSetAttribute(attn_mma,    cudaFuncAttributeMaxDynamicSharedMemorySize, ATTN_SMEM);

    gemm_qkv_tc<<<dim3(Mm / 128, Dd / 128, 3), 256, GEMM_SMEM>>>(x, Wq, Wk, Wv);
    attn_mma<<<dim3(Ss / 128, Hh, Bb), 256, ATTN_SMEM>>>();
    gemm_out_tc<<<dim3(Mm / 128, Dd / 128), 256, GEMM_SMEM>>>(Wo, out);
}

// round 5
// speedup vs baseline: 1.3810x; 1.3810x over previous
#include <cuda_runtime.h>
#include <cuda_bf16.h>
#include <float.h>
#include <stdint.h>

#define Bb 2
#define Ss 2048
#define Dd 768
#define Hh 12
#define DH 64
#define Mm (Bb*Ss)

// ---------------- scratch ----------------
__device__ float g_Q[(size_t)Bb*Hh*Ss*DH];
__device__ float g_K[(size_t)Bb*Hh*Ss*DH];
__device__ float g_V[(size_t)Bb*Hh*Ss*DH];
__device__ __nv_bfloat16 g_Oh[(size_t)Mm*Dd];
__device__ __nv_bfloat16 g_Ol[(size_t)Mm*Dd];
__device__ __nv_bfloat16 g_Xh[(size_t)Mm*Dd];
__device__ __nv_bfloat16 g_Xl[(size_t)Mm*Dd];
__device__ __nv_bfloat16 g_Wh[4][(size_t)Dd*Dd];
__device__ __nv_bfloat16 g_Wl[4][(size_t)Dd*Dd];

// ---------------- helpers ----------------
__device__ __forceinline__ uint32_t smem_u32(const void* p) {
    uint32_t a;
    asm("{ .reg .u64 t; cvta.to.shared.u64 t, %1; cvt.u32.u64 %0, t; }" : "=r"(a) : "l"(p));
    return a;
}
__device__ __forceinline__ void cp16(uint32_t dst, const void* src) {
    asm volatile("cp.async.cg.shared.global [%0], [%1], 16;"
        :: "r"(dst), "l"(__cvta_generic_to_global(src)));
}
__device__ __forceinline__ void cp_commit() { asm volatile("cp.async.commit_group;"); }
__device__ __forceinline__ void cp_wait0()  { asm volatile("cp.async.wait_group 0;"); }
__device__ __forceinline__ void cp_wait2()  { asm volatile("cp.async.wait_group 2;"); }

__device__ __forceinline__ float to_tf32(float x) {
    uint32_t u;
    asm("cvt.rna.tf32.f32 %0, %1;" : "=r"(u) : "f"(x));
    return __uint_as_float(u);
}
__device__ __forceinline__ uint32_t f2u(float x) { return __float_as_uint(x); }

// tf32 k8 MMA (attention)
__device__ __forceinline__ void mma8(float* d, const uint32_t* a, const uint32_t* b) {
    asm volatile("mma.sync.aligned.m16n8k8.row.col.f32.tf32.tf32.f32 "
        "{%0,%1,%2,%3}, {%4,%5,%6,%7}, {%8,%9}, {%0,%1,%2,%3};"
        : "+f"(d[0]), "+f"(d[1]), "+f"(d[2]), "+f"(d[3])
        : "r"(a[0]), "r"(a[1]), "r"(a[2]), "r"(a[3]), "r"(b[0]), "r"(b[1]));
}
// bf16 k16 MMA (dense GEMMs)
__device__ __forceinline__ void mma16(float* d, const uint32_t* a, const uint32_t* b) {
    asm volatile("mma.sync.aligned.m16n8k16.row.col.f32.bf16.bf16.f32 "
        "{%0,%1,%2,%3}, {%4,%5,%6,%7}, {%8,%9}, {%0,%1,%2,%3};"
        : "+f"(d[0]), "+f"(d[1]), "+f"(d[2]), "+f"(d[3])
        : "r"(a[0]), "r"(a[1]), "r"(a[2]), "r"(a[3]), "r"(b[0]), "r"(b[1]));
}
__device__ __forceinline__ void decb(float x, __nv_bfloat16& h, __nv_bfloat16& l) {
    h = __float2bfloat16_rn(x);
    l = __float2bfloat16_rn(x - __bfloat162float(h));
}

// ---------------- pre-pass: fp32 -> bf16 hi/lo ----------------
__global__ void conv_all(const float* __restrict__ x,
                         const float* __restrict__ wq, const float* __restrict__ wk,
                         const float* __restrict__ wv, const float* __restrict__ wo) {
    int i = blockIdx.x * blockDim.x + threadIdx.x;
    int stride = gridDim.x * blockDim.x;
    for (int t = i; t < Mm * Dd; t += stride) decb(x[t], g_Xh[t], g_Xl[t]);
    const float* ws[4] = {wq, wk, wv, wo};
    for (int w = 0; w < 4; w++)
        for (int t = i; t < Dd * Dd; t += stride) decb(ws[w][t], g_Wh[w][t], g_Wl[w][t]);
}

// ---------------- bf16x3 GEMM core ----------------
// CTA 128x128, BK=16, 256 threads (8 warps: wm 0..3, wn 0..1), warp tile 32x64.
// smem per stage (bytes): Ah[128][24] | Al | Bh | Bl, each 6144 B.
#define GSTG_B 24576
#define GCH 48

__device__ __forceinline__ uint32_t ldb(const __nv_bfloat16* arr, int row, int col) {
    return *(const uint32_t*)(arr + row * 24 + col);
}

__device__ __forceinline__ void gemm_core_bf3(const __nv_bfloat16* __restrict__ Ah,
                                              const __nv_bfloat16* __restrict__ Al,
                                              const __nv_bfloat16* __restrict__ Bh,
                                              const __nv_bfloat16* __restrict__ Bl,
                                              char* smc, float acc[2][8][4]) {
    const int tid = threadIdx.x;
    const int lane = tid & 31;
    const int wid = tid >> 5;
    const int wm = wid >> 1, wn = wid & 1;
    const int gr = lane >> 2, cL = lane & 3;

    uint32_t sb = smem_u32(smc);

    #pragma unroll
    for (int mt = 0; mt < 2; mt++)
        #pragma unroll
        for (int nt = 0; nt < 8; nt++)
            #pragma unroll
            for (int q = 0; q < 4; q++) acc[mt][nt][q] = 0.f;

    const int r = tid >> 1;                 // 0..127
    const int e = (tid & 1) << 3;           // 0 or 8 (bf16 cols)
    const uint32_t soff = (uint32_t)(r * 24 + e) * 2;   // byte offset in one array
    const size_t gbase = (size_t)r * Dd + e;

    #pragma unroll
    for (int c = 0; c < 3; c++) {
        uint32_t st = sb + c * GSTG_B;
        cp16(st + soff,          Ah + gbase + c * 16);
        cp16(st + 6144 + soff,   Al + gbase + c * 16);
        cp16(st + 12288 + soff,  Bh + gbase + c * 16);
        cp16(st + 18432 + soff,  Bl + gbase + c * 16);
        cp_commit();
    }

    for (int c = 0; c < GCH; c++) {
        cp_wait2();
        __syncthreads();
        if (c + 3 < GCH) {
            uint32_t st = sb + ((c + 3) & 3) * GSTG_B;
            cp16(st + soff,          Ah + gbase + (c + 3) * 16);
            cp16(st + 6144 + soff,   Al + gbase + (c + 3) * 16);
            cp16(st + 12288 + soff,  Bh + gbase + (c + 3) * 16);
            cp16(st + 18432 + soff,  Bl + gbase + (c + 3) * 16);
        }
        cp_commit();

        const char* stg = smc + (c & 3) * GSTG_B;
        const __nv_bfloat16* sAh = (const __nv_bfloat16*)stg;
        const __nv_bfloat16* sAl = (const __nv_bfloat16*)(stg + 6144);
        const __nv_bfloat16* sBh = (const __nv_bfloat16*)(stg + 12288);
        const __nv_bfloat16* sBl = (const __nv_bfloat16*)(stg + 18432);

        uint32_t ah[2][4], al[2][4];
        #pragma unroll
        for (int mt = 0; mt < 2; mt++) {
            int r0 = wm * 32 + mt * 16 + gr;
            ah[mt][0] = ldb(sAh, r0,     2 * cL);
            ah[mt][1] = ldb(sAh, r0 + 8, 2 * cL);
            ah[mt][2] = ldb(sAh, r0,     2 * cL + 8);
            ah[mt][3] = ldb(sAh, r0 + 8, 2 * cL + 8);
            al[mt][0] = ldb(sAl, r0,     2 * cL);
            al[mt][1] = ldb(sAl, r0 + 8, 2 * cL);
            al[mt][2] = ldb(sAl, r0,     2 * cL + 8);
            al[mt][3] = ldb(sAl, r0 + 8, 2 * cL + 8);
        }
        #pragma unroll
        for (int nt = 0; nt < 8; nt++) {
            int br = wn * 64 + nt * 8 + gr;
            uint32_t bh[2], bl[2];
            bh[0] = ldb(sBh, br, 2 * cL);
            bh[1] = ldb(sBh, br, 2 * cL + 8);
            bl[0] = ldb(sBl, br, 2 * cL);
            bl[1] = ldb(sBl, br, 2 * cL + 8);
            #pragma unroll
            for (int mt = 0; mt < 2; mt++) {
                mma16(acc[mt][nt], al[mt], bh);
                mma16(acc[mt][nt], ah[mt], bl);
                mma16(acc[mt][nt], ah[mt], bh);
            }
        }
    }
}

// QKV projection: scatter fp32 (tf32-rounded, Q pre-scaled) into [B,H,S,DH]
__global__ __launch_bounds__(256, 2) void gemm_qkv_tc() {
    extern __shared__ char smc[];
    const int z = blockIdx.z;
    float* Obuf = (z == 0) ? g_Q : (z == 1 ? g_K : g_V);
    const float scale = (z == 0) ? 0.125f : 1.0f;
    const int mBase = blockIdx.x * 128, nBase = blockIdx.y * 128;

    float acc[2][8][4];
    gemm_core_bf3(g_Xh + (size_t)mBase * Dd, g_Xl + (size_t)mBase * Dd,
                  g_Wh[z] + (size_t)nBase * Dd, g_Wl[z] + (size_t)nBase * Dd,
                  smc, acc);

    const int lane = threadIdx.x & 31, wid = threadIdx.x >> 5;
    const int wm = wid >> 1, wn = wid & 1;
    const int h = (nBase + wn * 64) >> 6;
    #pragma unroll
    for (int mt = 0; mt < 2; mt++) {
        int r0 = mBase + wm * 32 + mt * 16 + (lane >> 2);
        #pragma unroll
        for (int half = 0; half < 2; half++) {
            int row = r0 + half * 8;
            int bb = row >> 11, ssi = row & 2047;
            float* dst = Obuf + (((size_t)bb * Hh + h) * Ss + ssi) * DH;
            #pragma unroll
            for (int nt = 0; nt < 8; nt++) {
                int d = nt * 8 + 2 * (lane & 3);
                *(float2*)(dst + d) = make_float2(
                    to_tf32(acc[mt][nt][half * 2 + 0] * scale),
                    to_tf32(acc[mt][nt][half * 2 + 1] * scale));
            }
        }
    }
}

// output projection: fp32 store to d_out
__global__ __launch_bounds__(256, 2) void gemm_out_tc(float* __restrict__ C) {
    extern __shared__ char smc[];
    const int mBase = blockIdx.x * 128, nBase = blockIdx.y * 128;

    float acc[2][8][4];
    gemm_core_bf3(g_Oh + (size_t)mBase * Dd, g_Ol + (size_t)mBase * Dd,
                  g_Wh[3] + (size_t)nBase * Dd, g_Wl[3] + (size_t)nBase * Dd,
                  smc, acc);

    const int lane = threadIdx.x & 31, wid = threadIdx.x >> 5;
    const int wm = wid >> 1, wn = wid & 1;
    #pragma unroll
    for (int mt = 0; mt < 2; mt++) {
        int r0 = mBase + wm * 32 + mt * 16 + (lane >> 2);
        #pragma unroll
        for (int half = 0; half < 2; half++) {
            int row = r0 + half * 8;
            float* dst = C + (size_t)row * Dd + nBase + wn * 64;
            #pragma unroll
            for (int nt = 0; nt < 8; nt++) {
                int d = nt * 8 + 2 * (lane & 3);
                *(float2*)(dst + d) = make_float2(acc[mt][nt][half * 2 + 0],
                                                  acc[mt][nt][half * 2 + 1]);
            }
        }
    }
}

// ---------------- flash attention (R3-proven: 128 thr, 2 CTAs/SM) ----------------
// Qs[128][68], Ks[64][68], Vs[64][72], Ps[128][72]
#define QS_OFF 0
#define KS_OFF 8704
#define VS_OFF 13056
#define PS_OFF 17664

__global__ __launch_bounds__(128) void attn_mma() {
    extern __shared__ float sm[];
    float* Qs = sm + QS_OFF;
    float* Ks = sm + KS_OFF;
    float* Vs = sm + VS_OFF;
    float* Ps = sm + PS_OFF;

    const int tid = threadIdx.x;
    const int lane = tid & 31, wid = tid >> 5;
    const int qt = gridDim.x - 1 - blockIdx.x;
    const int h = blockIdx.y, b = blockIdx.z;

    const float* Qg = g_Q + (((size_t)b * Hh + h) * Ss + (size_t)qt * 128) * DH;
    const float* Kg = g_K + (((size_t)b * Hh + h) * Ss) * DH;
    const float* Vg = g_V + (((size_t)b * Hh + h) * Ss) * DH;

    uint32_t sQ = smem_u32(Qs), sK = smem_u32(Ks), sV = smem_u32(Vs);

    #pragma unroll
    for (int t = 0; t < 16; t++) {
        int idx = tid + t * 128;
        int r = idx >> 4, c = (idx & 15) * 4;
        cp16(sQ + (r * 68 + c) * 4, Qg + r * DH + c);
    }
    cp_commit();

    float o[2][8][4];
    float mrow[2][2], lrow[2][2];
    #pragma unroll
    for (int mt = 0; mt < 2; mt++) {
        mrow[mt][0] = mrow[mt][1] = -1e30f;
        lrow[mt][0] = lrow[mt][1] = 0.f;
        #pragma unroll
        for (int nt = 0; nt < 8; nt++)
            #pragma unroll
            for (int q = 0; q < 4; q++) o[mt][nt][q] = 0.f;
    }

    const int cL = lane & 3, rL = lane >> 2;
    const int ktMax = 2 * qt + 1;

    for (int kt = 0; kt <= ktMax; kt++) {
        __syncthreads();
        const float* Kp = Kg + (size_t)kt * 64 * DH;
        const float* Vp = Vg + (size_t)kt * 64 * DH;
        #pragma unroll
        for (int t = 0; t < 8; t++) {
            int idx = tid + t * 128;
            int r = idx >> 4, c = (idx & 15) * 4;
            cp16(sK + (r * 68 + c) * 4, Kp + r * DH + c);
            cp16(sV + (r * 72 + c) * 4, Vp + r * DH + c);
        }
        cp_commit();
        cp_wait0();
        __syncthreads();

        float s[2][8][4];
        #pragma unroll
        for (int mt = 0; mt < 2; mt++)
            #pragma unroll
            for (int nt = 0; nt < 8; nt++)
                #pragma unroll
                for (int q = 0; q < 4; q++) s[mt][nt][q] = 0.f;

        #pragma unroll
        for (int ks = 0; ks < 8; ks++) {
            const int kb = ks * 8 + cL;
            uint32_t bfr[8][2];
            #pragma unroll
            for (int nt = 0; nt < 8; nt++) {
                const float* kp = Ks + (nt * 8 + rL) * 68;
                bfr[nt][0] = f2u(kp[kb]);
                bfr[nt][1] = f2u(kp[kb + 4]);
            }
            #pragma unroll
            for (int mt = 0; mt < 2; mt++) {
                const float* qp = Qs + (wid * 32 + mt * 16 + rL) * 68;
                uint32_t a[4];
                a[0] = f2u(qp[kb]);
                a[1] = f2u(qp[8 * 68 + kb]);
                a[2] = f2u(qp[kb + 4]);
                a[3] = f2u(qp[8 * 68 + kb + 4]);
                #pragma unroll
                for (int nt = 0; nt < 8; nt++) mma8(s[mt][nt], a, bfr[nt]);
            }
        }

        if (kt >= 2 * qt) {
            #pragma unroll
            for (int mt = 0; mt < 2; mt++) {
                int rg0 = qt * 128 + wid * 32 + mt * 16 + rL;
                #pragma unroll
                for (int nt = 0; nt < 8; nt++) {
                    int cg = kt * 64 + nt * 8 + 2 * cL;
                    if (cg     > rg0)     s[mt][nt][0] = -1e30f;
                    if (cg + 1 > rg0)     s[mt][nt][1] = -1e30f;
                    if (cg     > rg0 + 8) s[mt][nt][2] = -1e30f;
                    if (cg + 1 > rg0 + 8) s[mt][nt][3] = -1e30f;
                }
            }
        }

        #pragma unroll
        for (int mt = 0; mt < 2; mt++) {
            float v0 = -1e30f, v1 = -1e30f;
            #pragma unroll
            for (int nt = 0; nt < 8; nt++) {
                v0 = fmaxf(v0, fmaxf(s[mt][nt][0], s[mt][nt][1]));
                v1 = fmaxf(v1, fmaxf(s[mt][nt][2], s[mt][nt][3]));
            }
            v0 = fmaxf(v0, __shfl_xor_sync(0xffffffffu, v0, 1));
            v0 = fmaxf(v0, __shfl_xor_sync(0xffffffffu, v0, 2));
            v1 = fmaxf(v1, __shfl_xor_sync(0xffffffffu, v1, 1));
            v1 = fmaxf(v1, __shfl_xor_sync(0xffffffffu, v1, 2));

            float mn0 = fmaxf(mrow[mt][0], v0);
            float mn1 = fmaxf(mrow[mt][1], v1);
            float cr0 = __expf(mrow[mt][0] - mn0);
            float cr1 = __expf(mrow[mt][1] - mn1);
            mrow[mt][0] = mn0; mrow[mt][1] = mn1;

            float rs0 = 0.f, rs1 = 0.f;
            float* prow0 = Ps + (wid * 32 + mt * 16 + rL) * 72;
            float* prow1 = prow0 + 8 * 72;
            #pragma unroll
            for (int nt = 0; nt < 8; nt++) {
                float p0 = __expf(s[mt][nt][0] - mn0);
                float p1 = __expf(s[mt][nt][1] - mn0);
                float p2 = __expf(s[mt][nt][2] - mn1);
                float p3 = __expf(s[mt][nt][3] - mn1);
                rs0 += p0 + p1; rs1 += p2 + p3;
                int cc = nt * 8 + 2 * cL;
                *(float2*)(prow0 + cc) = make_float2(to_tf32(p0), to_tf32(p1));
                *(float2*)(prow1 + cc) = make_float2(to_tf32(p2), to_tf32(p3));
            }
            rs0 += __shfl_xor_sync(0xffffffffu, rs0, 1);
            rs0 += __shfl_xor_sync(0xffffffffu, rs0, 2);
            rs1 += __shfl_xor_sync(0xffffffffu, rs1, 1);
            rs1 += __shfl_xor_sync(0xffffffffu, rs1, 2);
            lrow[mt][0] = lrow[mt][0] * cr0 + rs0;
            lrow[mt][1] = lrow[mt][1] * cr1 + rs1;
            #pragma unroll
            for (int nt = 0; nt < 8; nt++) {
                o[mt][nt][0] *= cr0; o[mt][nt][1] *= cr0;
                o[mt][nt][2] *= cr1; o[mt][nt][3] *= cr1;
            }
        }
        __syncwarp();

        #pragma unroll
        for (int ks = 0; ks < 8; ks++) {
            const int kb = ks * 8;
            uint32_t bfr[8][2];
            #pragma unroll
            for (int nt = 0; nt < 8; nt++) {
                bfr[nt][0] = f2u(Vs[(kb + cL) * 72 + nt * 8 + rL]);
                bfr[nt][1] = f2u(Vs[(kb + 4 + cL) * 72 + nt * 8 + rL]);
            }
            #pragma unroll
            for (int mt = 0; mt < 2; mt++) {
                const float* pp = Ps + (wid * 32 + mt * 16 + rL) * 72;
                uint32_t a[4];
                a[0] = f2u(pp[kb + cL]);
                a[1] = f2u(pp[8 * 72 + kb + cL]);
                a[2] = f2u(pp[kb + 4 + cL]);
                a[3] = f2u(pp[8 * 72 + kb + 4 + cL]);
                #pragma unroll
                for (int nt = 0; nt < 8; nt++) mma8(o[mt][nt], a, bfr[nt]);
            }
        }
    }

    // epilogue: normalize, decompose to bf16 hi/lo for the out-projection
    #pragma unroll
    for (int mt = 0; mt < 2; mt++) {
        float inv0 = 1.f / lrow[mt][0];
        float inv1 = 1.f / lrow[mt][1];
        int r0 = qt * 128 + wid * 32 + mt * 16 + rL;
        size_t base0 = ((size_t)b * Ss + r0) * Dd + h * DH;
        size_t base1 = base0 + 8 * Dd;
        #pragma unroll
        for (int nt = 0; nt < 8; nt++) {
            int cc = nt * 8 + 2 * cL;
            float x0 = o[mt][nt][0] * inv0, x1 = o[mt][nt][1] * inv0;
            float x2 = o[mt][nt][2] * inv1, x3 = o[mt][nt][3] * inv1;
            __nv_bfloat16 h0, l0, h1, l1, h2, l2, h3, l3;
            decb(x0, h0, l0); decb(x1, h1, l1);
            decb(x2, h2, l2); decb(x3, h3, l3);
            *(__nv_bfloat162*)(g_Oh + base0 + cc) = __nv_bfloat162(h0, h1);
            *(__nv_bfloat162*)(g_Ol + base0 + cc) = __nv_bfloat162(l0, l1);
            *(__nv_bfloat162*)(g_Oh + base1 + cc) = __nv_bfloat162(h2, h3);
            *(__nv_bfloat162*)(g_Ol + base1 + cc) = __nv_bfloat162(l2, l3);
        }
    }
}

// ---------------------------------------------------------------------------

extern "C" void kernel_launch(void* const* d_in, const int* in_sizes, int n_in,
                              void* d_out, int out_size)
{
    const float* x  = (const float*)d_in[0];
    const float* Wq = (const float*)d_in[1];
    const float* Wk = (const float*)d_in[2];
    const float* Wv = (const float*)d_in[3];
    const float* Wo = (const float*)d_in[4];
    float* out = (float*)d_out;

    const int GEMM_SMEM = 4 * GSTG_B;                        // 98304
    const int ATTN_SMEM = (PS_OFF + 128 * 72) * (int)sizeof(float);  // 107520

    cudaFuncSetAttribute(gemm_qkv_tc, cudaFuncAttributeMaxDynamicSharedMemorySize, GEMM_SMEM);
    cudaFuncSetAttribute(gemm_out_tc, cudaFuncAttributeMaxDynamicSharedMemorySize, GEMM_SMEM);
    cudaFuncSetAttribute(attn_mma,    cudaFuncAttributeMaxDynamicSharedMemorySize, ATTN_SMEM);

    conv_all<<<512, 256>>>(x, Wq, Wk, Wv, Wo);
    gemm_qkv_tc<<<dim3(Mm / 128, Dd / 128, 3), 256, GEMM_SMEM>>>();
    attn_mma<<<dim3(Ss / 128, Hh, Bb), 128, ATTN_SMEM>>>();
    gemm_out_tc<<<dim3(Mm / 128, Dd / 128), 256, GEMM_SMEM>>>(out);
}

// round 6
// speedup vs baseline: 1.4823x; 1.0733x over previous
#include <cuda_runtime.h>
#include <cuda_bf16.h>
#include <float.h>
#include <stdint.h>

#define Bb 2
#define Ss 2048
#define Dd 768
#define Hh 12
#define DH 64
#define Mm (Bb*Ss)

// ---------------- scratch ----------------
__device__ float g_Q[(size_t)Bb*Hh*Ss*DH];
__device__ float g_K[(size_t)Bb*Hh*Ss*DH];
__device__ float g_V[(size_t)Bb*Hh*Ss*DH];
__device__ __nv_bfloat16 g_Oh[(size_t)Mm*Dd];
__device__ __nv_bfloat16 g_Ol[(size_t)Mm*Dd];
__device__ __nv_bfloat16 g_Xh[(size_t)Mm*Dd];
__device__ __nv_bfloat16 g_Xl[(size_t)Mm*Dd];
__device__ __nv_bfloat16 g_Wh[4][(size_t)Dd*Dd];
__device__ __nv_bfloat16 g_Wl[4][(size_t)Dd*Dd];

// ---------------- helpers ----------------
__device__ __forceinline__ uint32_t smem_u32(const void* p) {
    uint32_t a;
    asm("{ .reg .u64 t; cvta.to.shared.u64 t, %1; cvt.u32.u64 %0, t; }" : "=r"(a) : "l"(p));
    return a;
}
__device__ __forceinline__ void cp16(uint32_t dst, const void* src) {
    asm volatile("cp.async.cg.shared.global [%0], [%1], 16;"
        :: "r"(dst), "l"(__cvta_generic_to_global(src)));
}
__device__ __forceinline__ void cp_commit() { asm volatile("cp.async.commit_group;"); }
__device__ __forceinline__ void cp_wait0()  { asm volatile("cp.async.wait_group 0;"); }
__device__ __forceinline__ void cp_wait2()  { asm volatile("cp.async.wait_group 2;"); }

__device__ __forceinline__ float to_tf32(float x) {
    uint32_t u;
    asm("cvt.rna.tf32.f32 %0, %1;" : "=r"(u) : "f"(x));
    return __uint_as_float(u);
}
__device__ __forceinline__ uint32_t f2u(float x) { return __float_as_uint(x); }

// tf32 k8 MMA (attention)
__device__ __forceinline__ void mma8(float* d, const uint32_t* a, const uint32_t* b) {
    asm volatile("mma.sync.aligned.m16n8k8.row.col.f32.tf32.tf32.f32 "
        "{%0,%1,%2,%3}, {%4,%5,%6,%7}, {%8,%9}, {%0,%1,%2,%3};"
        : "+f"(d[0]), "+f"(d[1]), "+f"(d[2]), "+f"(d[3])
        : "r"(a[0]), "r"(a[1]), "r"(a[2]), "r"(a[3]), "r"(b[0]), "r"(b[1]));
}
// bf16 k16 MMA (dense GEMMs)
__device__ __forceinline__ void mma16(float* d, const uint32_t* a, const uint32_t* b) {
    asm volatile("mma.sync.aligned.m16n8k16.row.col.f32.bf16.bf16.f32 "
        "{%0,%1,%2,%3}, {%4,%5,%6,%7}, {%8,%9}, {%0,%1,%2,%3};"
        : "+f"(d[0]), "+f"(d[1]), "+f"(d[2]), "+f"(d[3])
        : "r"(a[0]), "r"(a[1]), "r"(a[2]), "r"(a[3]), "r"(b[0]), "r"(b[1]));
}
__device__ __forceinline__ void ldm4(uint32_t* r, uint32_t addr) {
    asm volatile("ldmatrix.sync.aligned.m8n8.x4.shared.b16 {%0,%1,%2,%3}, [%4];"
        : "=r"(r[0]), "=r"(r[1]), "=r"(r[2]), "=r"(r[3]) : "r"(addr));
}
__device__ __forceinline__ void decb(float x, __nv_bfloat16& h, __nv_bfloat16& l) {
    h = __float2bfloat16_rn(x);
    l = __float2bfloat16_rn(x - __bfloat162float(h));
}

// ---------------- pre-pass: fp32 -> bf16 hi/lo ----------------
__global__ void conv_all(const float* __restrict__ x,
                         const float* __restrict__ wq, const float* __restrict__ wk,
                         const float* __restrict__ wv, const float* __restrict__ wo) {
    int i = blockIdx.x * blockDim.x + threadIdx.x;
    int stride = gridDim.x * blockDim.x;
    for (int t = i; t < Mm * Dd; t += stride) decb(x[t], g_Xh[t], g_Xl[t]);
    const float* ws[4] = {wq, wk, wv, wo};
    for (int w = 0; w < 4; w++)
        for (int t = i; t < Dd * Dd; t += stride) decb(ws[w][t], g_Wh[w][t], g_Wl[w][t]);
}

// ---------------- bf16x3 GEMM core with ldmatrix fragments ----------------
// CTA 128x128, BK=16, 256 threads (8 warps: wm 0..3, wn 0..1), warp tile 32x64.
// smem per stage: Ah[128][24] | Al | Bh | Bl bf16, each 6144 B (row stride 48B
// -> ldmatrix 8-row pattern hits all 32 banks, conflict-free).
#define GSTG_B 24576
#define GCH 48

__device__ __forceinline__ void gemm_core_bf3(const __nv_bfloat16* __restrict__ Ah,
                                              const __nv_bfloat16* __restrict__ Al,
                                              const __nv_bfloat16* __restrict__ Bh,
                                              const __nv_bfloat16* __restrict__ Bl,
                                              char* smc, float acc[2][8][4]) {
    const int tid = threadIdx.x;
    const int lane = tid & 31;
    const int wid = tid >> 5;
    const int wm = wid >> 1, wn = wid & 1;

    uint32_t sb = smem_u32(smc);

    #pragma unroll
    for (int mt = 0; mt < 2; mt++)
        #pragma unroll
        for (int nt = 0; nt < 8; nt++)
            #pragma unroll
            for (int q = 0; q < 4; q++) acc[mt][nt][q] = 0.f;

    // cp.async mapping: thread -> (row, 8-elem half)
    const int r = tid >> 1;
    const int e = (tid & 1) << 3;
    const uint32_t soff = (uint32_t)(r * 24 + e) * 2;
    const size_t gbase = (size_t)r * Dd + e;

    // ldmatrix within-stage offsets (bytes)
    const int arow = lane & 15, acol = (lane >> 4) << 3;
    const uint32_t aoff0 = (uint32_t)((wm * 32 + arow) * 24 + acol) * 2;        // mt=0
    const uint32_t aoff1 = aoff0 + 16 * 24 * 2;                                  // mt=1
    const int brow = ((lane >> 4) << 3) + (lane & 7), bcol = ((lane >> 3) & 1) << 3;
    uint32_t boff[4];
    #pragma unroll
    for (int p = 0; p < 4; p++)
        boff[p] = (uint32_t)((wn * 64 + p * 16 + brow) * 24 + bcol) * 2;

    #pragma unroll
    for (int c = 0; c < 3; c++) {
        uint32_t st = sb + c * GSTG_B;
        cp16(st + soff,          Ah + gbase + c * 16);
        cp16(st + 6144 + soff,   Al + gbase + c * 16);
        cp16(st + 12288 + soff,  Bh + gbase + c * 16);
        cp16(st + 18432 + soff,  Bl + gbase + c * 16);
        cp_commit();
    }

    for (int c = 0; c < GCH; c++) {
        cp_wait2();
        __syncthreads();
        if (c + 3 < GCH) {
            uint32_t st = sb + ((c + 3) & 3) * GSTG_B;
            cp16(st + soff,          Ah + gbase + (c + 3) * 16);
            cp16(st + 6144 + soff,   Al + gbase + (c + 3) * 16);
            cp16(st + 12288 + soff,  Bh + gbase + (c + 3) * 16);
            cp16(st + 18432 + soff,  Bl + gbase + (c + 3) * 16);
        }
        cp_commit();

        const uint32_t st  = sb + (c & 3) * GSTG_B;
        const uint32_t stA = st, stAl = st + 6144, stB = st + 12288, stBl = st + 18432;

        uint32_t ah[2][4], al[2][4];
        ldm4(ah[0], stA  + aoff0);
        ldm4(ah[1], stA  + aoff1);
        ldm4(al[0], stAl + aoff0);
        ldm4(al[1], stAl + aoff1);

        // B double-buffered over nt-pairs: bh/bl[buf][4] = {b_nt(2), b_nt+1(2)}
        uint32_t bh[2][4], bl[2][4];
        ldm4(bh[0], stB  + boff[0]);
        ldm4(bl[0], stBl + boff[0]);
        #pragma unroll
        for (int p = 0; p < 4; p++) {
            const int cur = p & 1, nxt = cur ^ 1;
            if (p < 3) {
                ldm4(bh[nxt], stB  + boff[p + 1]);
                ldm4(bl[nxt], stBl + boff[p + 1]);
            }
            #pragma unroll
            for (int j = 0; j < 2; j++) {
                const int nt = p * 2 + j;
                #pragma unroll
                for (int mt = 0; mt < 2; mt++) {
                    mma16(acc[mt][nt], al[mt], &bh[cur][2 * j]);
                    mma16(acc[mt][nt], ah[mt], &bl[cur][2 * j]);
                    mma16(acc[mt][nt], ah[mt], &bh[cur][2 * j]);
                }
            }
        }
    }
}

// QKV projection: scatter fp32 (tf32-rounded, Q pre-scaled) into [B,H,S,DH]
__global__ __launch_bounds__(256, 2) void gemm_qkv_tc() {
    extern __shared__ char smc[];
    const int z = blockIdx.z;
    float* Obuf = (z == 0) ? g_Q : (z == 1 ? g_K : g_V);
    const float scale = (z == 0) ? 0.125f : 1.0f;
    const int mBase = blockIdx.x * 128, nBase = blockIdx.y * 128;

    float acc[2][8][4];
    gemm_core_bf3(g_Xh + (size_t)mBase * Dd, g_Xl + (size_t)mBase * Dd,
                  g_Wh[z] + (size_t)nBase * Dd, g_Wl[z] + (size_t)nBase * Dd,
                  smc, acc);

    const int lane = threadIdx.x & 31, wid = threadIdx.x >> 5;
    const int wm = wid >> 1, wn = wid & 1;
    const int h = (nBase + wn * 64) >> 6;
    #pragma unroll
    for (int mt = 0; mt < 2; mt++) {
        int r0 = mBase + wm * 32 + mt * 16 + (lane >> 2);
        #pragma unroll
        for (int half = 0; half < 2; half++) {
            int row = r0 + half * 8;
            int bb = row >> 11, ssi = row & 2047;
            float* dst = Obuf + (((size_t)bb * Hh + h) * Ss + ssi) * DH;
            #pragma unroll
            for (int nt = 0; nt < 8; nt++) {
                int d = nt * 8 + 2 * (lane & 3);
                *(float2*)(dst + d) = make_float2(
                    to_tf32(acc[mt][nt][half * 2 + 0] * scale),
                    to_tf32(acc[mt][nt][half * 2 + 1] * scale));
            }
        }
    }
}

// output projection: fp32 store to d_out
__global__ __launch_bounds__(256, 2) void gemm_out_tc(float* __restrict__ C) {
    extern __shared__ char smc[];
    const int mBase = blockIdx.x * 128, nBase = blockIdx.y * 128;

    float acc[2][8][4];
    gemm_core_bf3(g_Oh + (size_t)mBase * Dd, g_Ol + (size_t)mBase * Dd,
                  g_Wh[3] + (size_t)nBase * Dd, g_Wl[3] + (size_t)nBase * Dd,
                  smc, acc);

    const int lane = threadIdx.x & 31, wid = threadIdx.x >> 5;
    const int wm = wid >> 1, wn = wid & 1;
    #pragma unroll
    for (int mt = 0; mt < 2; mt++) {
        int r0 = mBase + wm * 32 + mt * 16 + (lane >> 2);
        #pragma unroll
        for (int half = 0; half < 2; half++) {
            int row = r0 + half * 8;
            float* dst = C + (size_t)row * Dd + nBase + wn * 64;
            #pragma unroll
            for (int nt = 0; nt < 8; nt++) {
                int d = nt * 8 + 2 * (lane & 3);
                *(float2*)(dst + d) = make_float2(acc[mt][nt][half * 2 + 0],
                                                  acc[mt][nt][half * 2 + 1]);
            }
        }
    }
}

// ---------------- flash attention (unchanged from R5) ----------------
#define QS_OFF 0
#define KS_OFF 8704
#define VS_OFF 13056
#define PS_OFF 17664

__global__ __launch_bounds__(128) void attn_mma() {
    extern __shared__ float sm[];
    float* Qs = sm + QS_OFF;
    float* Ks = sm + KS_OFF;
    float* Vs = sm + VS_OFF;
    float* Ps = sm + PS_OFF;

    const int tid = threadIdx.x;
    const int lane = tid & 31, wid = tid >> 5;
    const int qt = gridDim.x - 1 - blockIdx.x;
    const int h = blockIdx.y, b = blockIdx.z;

    const float* Qg = g_Q + (((size_t)b * Hh + h) * Ss + (size_t)qt * 128) * DH;
    const float* Kg = g_K + (((size_t)b * Hh + h) * Ss) * DH;
    const float* Vg = g_V + (((size_t)b * Hh + h) * Ss) * DH;

    uint32_t sQ = smem_u32(Qs), sK = smem_u32(Ks), sV = smem_u32(Vs);

    #pragma unroll
    for (int t = 0; t < 16; t++) {
        int idx = tid + t * 128;
        int r = idx >> 4, c = (idx & 15) * 4;
        cp16(sQ + (r * 68 + c) * 4, Qg + r * DH + c);
    }
    cp_commit();

    float o[2][8][4];
    float mrow[2][2], lrow[2][2];
    #pragma unroll
    for (int mt = 0; mt < 2; mt++) {
        mrow[mt][0] = mrow[mt][1] = -1e30f;
        lrow[mt][0] = lrow[mt][1] = 0.f;
        #pragma unroll
        for (int nt = 0; nt < 8; nt++)
            #pragma unroll
            for (int q = 0; q < 4; q++) o[mt][nt][q] = 0.f;
    }

    const int cL = lane & 3, rL = lane >> 2;
    const int ktMax = 2 * qt + 1;

    for (int kt = 0; kt <= ktMax; kt++) {
        __syncthreads();
        const float* Kp = Kg + (size_t)kt * 64 * DH;
        const float* Vp = Vg + (size_t)kt * 64 * DH;
        #pragma unroll
        for (int t = 0; t < 8; t++) {
            int idx = tid + t * 128;
            int r = idx >> 4, c = (idx & 15) * 4;
            cp16(sK + (r * 68 + c) * 4, Kp + r * DH + c);
            cp16(sV + (r * 72 + c) * 4, Vp + r * DH + c);
        }
        cp_commit();
        cp_wait0();
        __syncthreads();

        float s[2][8][4];
        #pragma unroll
        for (int mt = 0; mt < 2; mt++)
            #pragma unroll
            for (int nt = 0; nt < 8; nt++)
                #pragma unroll
                for (int q = 0; q < 4; q++) s[mt][nt][q] = 0.f;

        #pragma unroll
        for (int ks = 0; ks < 8; ks++) {
            const int kb = ks * 8 + cL;
            uint32_t bfr[8][2];
            #pragma unroll
            for (int nt = 0; nt < 8; nt++) {
                const float* kp = Ks + (nt * 8 + rL) * 68;
                bfr[nt][0] = f2u(kp[kb]);
                bfr[nt][1] = f2u(kp[kb + 4]);
            }
            #pragma unroll
            for (int mt = 0; mt < 2; mt++) {
                const float* qp = Qs + (wid * 32 + mt * 16 + rL) * 68;
                uint32_t a[4];
                a[0] = f2u(qp[kb]);
                a[1] = f2u(qp[8 * 68 + kb]);
                a[2] = f2u(qp[kb + 4]);
                a[3] = f2u(qp[8 * 68 + kb + 4]);
                #pragma unroll
                for (int nt = 0; nt < 8; nt++) mma8(s[mt][nt], a, bfr[nt]);
            }
        }

        if (kt >= 2 * qt) {
            #pragma unroll
            for (int mt = 0; mt < 2; mt++) {
                int rg0 = qt * 128 + wid * 32 + mt * 16 + rL;
                #pragma unroll
                for (int nt = 0; nt < 8; nt++) {
                    int cg = kt * 64 + nt * 8 + 2 * cL;
                    if (cg     > rg0)     s[mt][nt][0] = -1e30f;
                    if (cg + 1 > rg0)     s[mt][nt][1] = -1e30f;
                    if (cg     > rg0 + 8) s[mt][nt][2] = -1e30f;
                    if (cg + 1 > rg0 + 8) s[mt][nt][3] = -1e30f;
                }
            }
        }

        #pragma unroll
        for (int mt = 0; mt < 2; mt++) {
            float v0 = -1e30f, v1 = -1e30f;
            #pragma unroll
            for (int nt = 0; nt < 8; nt++) {
                v0 = fmaxf(v0, fmaxf(s[mt][nt][0], s[mt][nt][1]));
                v1 = fmaxf(v1, fmaxf(s[mt][nt][2], s[mt][nt][3]));
            }
            v0 = fmaxf(v0, __shfl_xor_sync(0xffffffffu, v0, 1));
            v0 = fmaxf(v0, __shfl_xor_sync(0xffffffffu, v0, 2));
            v1 = fmaxf(v1, __shfl_xor_sync(0xffffffffu, v1, 1));
            v1 = fmaxf(v1, __shfl_xor_sync(0xffffffffu, v1, 2));

            float mn0 = fmaxf(mrow[mt][0], v0);
            float mn1 = fmaxf(mrow[mt][1], v1);
            float cr0 = __expf(mrow[mt][0] - mn0);
            float cr1 = __expf(mrow[mt][1] - mn1);
            mrow[mt][0] = mn0; mrow[mt][1] = mn1;

            float rs0 = 0.f, rs1 = 0.f;
            float* prow0 = Ps + (wid * 32 + mt * 16 + rL) * 72;
            float* prow1 = prow0 + 8 * 72;
            #pragma unroll
            for (int nt = 0; nt < 8; nt++) {
                float p0 = __expf(s[mt][nt][0] - mn0);
                float p1 = __expf(s[mt][nt][1] - mn0);
                float p2 = __expf(s[mt][nt][2] - mn1);
                float p3 = __expf(s[mt][nt][3] - mn1);
                rs0 += p0 + p1; rs1 += p2 + p3;
                int cc = nt * 8 + 2 * cL;
                *(float2*)(prow0 + cc) = make_float2(to_tf32(p0), to_tf32(p1));
                *(float2*)(prow1 + cc) = make_float2(to_tf32(p2), to_tf32(p3));
            }
            rs0 += __shfl_xor_sync(0xffffffffu, rs0, 1);
            rs0 += __shfl_xor_sync(0xffffffffu, rs0, 2);
            rs1 += __shfl_xor_sync(0xffffffffu, rs1, 1);
            rs1 += __shfl_xor_sync(0xffffffffu, rs1, 2);
            lrow[mt][0] = lrow[mt][0] * cr0 + rs0;
            lrow[mt][1] = lrow[mt][1] * cr1 + rs1;
            #pragma unroll
            for (int nt = 0; nt < 8; nt++) {
                o[mt][nt][0] *= cr0; o[mt][nt][1] *= cr0;
                o[mt][nt][2] *= cr1; o[mt][nt][3] *= cr1;
            }
        }
        __syncwarp();

        #pragma unroll
        for (int ks = 0; ks < 8; ks++) {
            const int kb = ks * 8;
            uint32_t bfr[8][2];
            #pragma unroll
            for (int nt = 0; nt < 8; nt++) {
                bfr[nt][0] = f2u(Vs[(kb + cL) * 72 + nt * 8 + rL]);
                bfr[nt][1] = f2u(Vs[(kb + 4 + cL) * 72 + nt * 8 + rL]);
            }
            #pragma unroll
            for (int mt = 0; mt < 2; mt++) {
                const float* pp = Ps + (wid * 32 + mt * 16 + rL) * 72;
                uint32_t a[4];
                a[0] = f2u(pp[kb + cL]);
                a[1] = f2u(pp[8 * 72 + kb + cL]);
                a[2] = f2u(pp[kb + 4 + cL]);
                a[3] = f2u(pp[8 * 72 + kb + 4 + cL]);
                #pragma unroll
                for (int nt = 0; nt < 8; nt++) mma8(o[mt][nt], a, bfr[nt]);
            }
        }
    }

    #pragma unroll
    for (int mt = 0; mt < 2; mt++) {
        float inv0 = 1.f / lrow[mt][0];
        float inv1 = 1.f / lrow[mt][1];
        int r0 = qt * 128 + wid * 32 + mt * 16 + rL;
        size_t base0 = ((size_t)b * Ss + r0) * Dd + h * DH;
        size_t base1 = base0 + 8 * Dd;
        #pragma unroll
        for (int nt = 0; nt < 8; nt++) {
            int cc = nt * 8 + 2 * cL;
            float x0 = o[mt][nt][0] * inv0, x1 = o[mt][nt][1] * inv0;
            float x2 = o[mt][nt][2] * inv1, x3 = o[mt][nt][3] * inv1;
            __nv_bfloat16 h0, l0, h1, l1, h2, l2, h3, l3;
            decb(x0, h0, l0); decb(x1, h1, l1);
            decb(x2, h2, l2); decb(x3, h3, l3);
            *(__nv_bfloat162*)(g_Oh + base0 + cc) = __nv_bfloat162(h0, h1);
            *(__nv_bfloat162*)(g_Ol + base0 + cc) = __nv_bfloat162(l0, l1);
            *(__nv_bfloat162*)(g_Oh + base1 + cc) = __nv_bfloat162(h2, h3);
            *(__nv_bfloat162*)(g_Ol + base1 + cc) = __nv_bfloat162(l2, l3);
        }
    }
}

// ---------------------------------------------------------------------------

extern "C" void kernel_launch(void* const* d_in, const int* in_sizes, int n_in,
                              void* d_out, int out_size)
{
    const float* x  = (const float*)d_in[0];
    const float* Wq = (const float*)d_in[1];
    const float* Wk = (const float*)d_in[2];
    const float* Wv = (const float*)d_in[3];
    const float* Wo = (const float*)d_in[4];
    float* out = (float*)d_out;

    const int GEMM_SMEM = 4 * GSTG_B;
    const int ATTN_SMEM = (PS_OFF + 128 * 72) * (int)sizeof(float);

    cudaFuncSetAttribute(gemm_qkv_tc, cudaFuncAttributeMaxDynamicSharedMemorySize, GEMM_SMEM);
    cudaFuncSetAttribute(gemm_out_tc, cudaFuncAttributeMaxDynamicSharedMemorySize, GEMM_SMEM);
    cudaFuncSetAttribute(attn_mma,    cudaFuncAttributeMaxDynamicSharedMemorySize, ATTN_SMEM);

    conv_all<<<512, 256>>>(x, Wq, Wk, Wv, Wo);
    gemm_qkv_tc<<<dim3(Mm / 128, Dd / 128, 3), 256, GEMM_SMEM>>>();
    attn_mma<<<dim3(Ss / 128, Hh, Bb), 128, ATTN_SMEM>>>();
    gemm_out_tc<<<dim3(Mm / 128, Dd / 128), 256, GEMM_SMEM>>>(out);
}

// round 7
// speedup vs baseline: 1.5804x; 1.0662x over previous
#include <cuda_runtime.h>
#include <cuda_bf16.h>
#include <float.h>
#include <stdint.h>

#define Bb 2
#define Ss 2048
#define Dd 768
#define Hh 12
#define DH 64
#define Mm (Bb*Ss)

// ---------------- scratch ----------------
__device__ float g_Q[(size_t)Bb*Hh*Ss*DH];
__device__ float g_K[(size_t)Bb*Hh*Ss*DH];
__device__ float g_V[(size_t)Bb*Hh*Ss*DH];
__device__ __nv_bfloat16 g_Oh[(size_t)Mm*Dd];
__device__ __nv_bfloat16 g_Ol[(size_t)Mm*Dd];
__device__ __nv_bfloat16 g_Xh[(size_t)Mm*Dd];
__device__ __nv_bfloat16 g_Xl[(size_t)Mm*Dd];
__device__ __nv_bfloat16 g_Wh[4][(size_t)Dd*Dd];
__device__ __nv_bfloat16 g_Wl[4][(size_t)Dd*Dd];

// ---------------- helpers ----------------
__device__ __forceinline__ uint32_t smem_u32(const void* p) {
    uint32_t a;
    asm("{ .reg .u64 t; cvta.to.shared.u64 t, %1; cvt.u32.u64 %0, t; }" : "=r"(a) : "l"(p));
    return a;
}
__device__ __forceinline__ void cp16(uint32_t dst, const void* src) {
    asm volatile("cp.async.cg.shared.global [%0], [%1], 16;"
        :: "r"(dst), "l"(__cvta_generic_to_global(src)));
}
__device__ __forceinline__ void cp_commit() { asm volatile("cp.async.commit_group;"); }
__device__ __forceinline__ void cp_wait0()  { asm volatile("cp.async.wait_group 0;"); }

__device__ __forceinline__ float to_tf32(float x) {
    uint32_t u;
    asm("cvt.rna.tf32.f32 %0, %1;" : "=r"(u) : "f"(x));
    return __uint_as_float(u);
}
__device__ __forceinline__ uint32_t f2u(float x) { return __float_as_uint(x); }

// tf32 k8 MMA (attention)
__device__ __forceinline__ void mma8(float* d, const uint32_t* a, const uint32_t* b) {
    asm volatile("mma.sync.aligned.m16n8k8.row.col.f32.tf32.tf32.f32 "
        "{%0,%1,%2,%3}, {%4,%5,%6,%7}, {%8,%9}, {%0,%1,%2,%3};"
        : "+f"(d[0]), "+f"(d[1]), "+f"(d[2]), "+f"(d[3])
        : "r"(a[0]), "r"(a[1]), "r"(a[2]), "r"(a[3]), "r"(b[0]), "r"(b[1]));
}
// bf16 k16 MMA (dense GEMMs)
__device__ __forceinline__ void mma16(float* d, const uint32_t* a, const uint32_t* b) {
    asm volatile("mma.sync.aligned.m16n8k16.row.col.f32.bf16.bf16.f32 "
        "{%0,%1,%2,%3}, {%4,%5,%6,%7}, {%8,%9}, {%0,%1,%2,%3};"
        : "+f"(d[0]), "+f"(d[1]), "+f"(d[2]), "+f"(d[3])
        : "r"(a[0]), "r"(a[1]), "r"(a[2]), "r"(a[3]), "r"(b[0]), "r"(b[1]));
}
__device__ __forceinline__ void ldm4(uint32_t* r, uint32_t addr) {
    asm volatile("ldmatrix.sync.aligned.m8n8.x4.shared.b16 {%0,%1,%2,%3}, [%4];"
        : "=r"(r[0]), "=r"(r[1]), "=r"(r[2]), "=r"(r[3]) : "r"(addr));
}
__device__ __forceinline__ void decb(float x, __nv_bfloat16& h, __nv_bfloat16& l) {
    h = __float2bfloat16_rn(x);
    l = __float2bfloat16_rn(x - __bfloat162float(h));
}

// ---------------- pre-pass: fp32 -> bf16 hi/lo ----------------
__global__ void conv_all(const float* __restrict__ x,
                         const float* __restrict__ wq, const float* __restrict__ wk,
                         const float* __restrict__ wv, const float* __restrict__ wo) {
    int i = blockIdx.x * blockDim.x + threadIdx.x;
    int stride = gridDim.x * blockDim.x;
    for (int t = i; t < Mm * Dd; t += stride) decb(x[t], g_Xh[t], g_Xl[t]);
    const float* ws[4] = {wq, wk, wv, wo};
    for (int w = 0; w < 4; w++)
        for (int t = i; t < Dd * Dd; t += stride) decb(ws[w][t], g_Wh[w][t], g_Wl[w][t]);
}

// ---------------- bf16x3 GEMM core, BK=32, 2-stage double buffer ----------------
// CTA 128x128, 256 threads (8 warps: wm 0..3, wn 0..1), warp tile 32x64.
// Stage layout (bytes): Ah[128][40] 10240 | Al 10240 | Bh 10240 | Bl 10240 = 40960.
// Row stride 80 B -> ldmatrix 8-row bank walk {0,20,8,28,16,4,24,12}: conflict-free.
#define GSTG_B 40960
#define GCH32 24            // 768 / 32

__device__ __forceinline__ void gemm_core_bf3(const __nv_bfloat16* __restrict__ Ah,
                                              const __nv_bfloat16* __restrict__ Al,
                                              const __nv_bfloat16* __restrict__ Bh,
                                              const __nv_bfloat16* __restrict__ Bl,
                                              char* smc, float acc[2][8][4]) {
    const int tid = threadIdx.x;
    const int lane = tid & 31;
    const int wid = tid >> 5;
    const int wm = wid >> 1, wn = wid & 1;

    uint32_t sb = smem_u32(smc);

    #pragma unroll
    for (int mt = 0; mt < 2; mt++)
        #pragma unroll
        for (int nt = 0; nt < 8; nt++)
            #pragma unroll
            for (int q = 0; q < 4; q++) acc[mt][nt][q] = 0.f;

    // cp.async mapping: each thread moves 2x16B per array (512 segs / 256 thr).
    // idx = t*256+tid: row = idx>>2 (0..127), seg = idx&3 (8 bf16 each).
    const int r0l = tid >> 2, s0l = tid & 3;
    const int r1l = (256 + tid) >> 2, s1l = tid & 3;   // (256+tid)&3 == tid&3
    const uint32_t so0 = (uint32_t)(r0l * 80 + s0l * 16);
    const uint32_t so1 = (uint32_t)(r1l * 80 + s1l * 16);
    const size_t go0 = (size_t)r0l * Dd + s0l * 8;
    const size_t go1 = (size_t)r1l * Dd + s1l * 8;

    // ldmatrix offsets (bytes within stage, before kh*32 adjustment)
    const int arow = lane & 15, acolb = ((lane >> 4) << 4);
    const uint32_t aoff0 = (uint32_t)((wm * 32 + arow) * 80) + acolb;
    const uint32_t aoff1 = aoff0 + 16 * 80;
    const int brow = ((lane >> 4) << 3) + (lane & 7);
    const int bcolb = (((lane >> 3) & 1) << 4);
    uint32_t boff[4];
    #pragma unroll
    for (int p = 0; p < 4; p++)
        boff[p] = (uint32_t)((wn * 64 + p * 16 + brow) * 80) + bcolb;

    // prologue: chunk 0 -> stage 0
    {
        cp16(sb + so0,          Ah + go0);
        cp16(sb + so1,          Ah + go1);
        cp16(sb + 10240 + so0,  Al + go0);
        cp16(sb + 10240 + so1,  Al + go1);
        cp16(sb + 20480 + so0,  Bh + go0);
        cp16(sb + 20480 + so1,  Bh + go1);
        cp16(sb + 30720 + so0,  Bl + go0);
        cp16(sb + 30720 + so1,  Bl + go1);
        cp_commit();
    }

    for (int c = 0; c < GCH32; c++) {
        cp_wait0();          // chunk c resident
        __syncthreads();     // all warps done reading stage (c-1)&1 (target of next load)
        if (c + 1 < GCH32) {
            uint32_t st = sb + ((c + 1) & 1) * GSTG_B;
            const size_t kq = (size_t)(c + 1) * 32;
            cp16(st + so0,          Ah + go0 + kq);
            cp16(st + so1,          Ah + go1 + kq);
            cp16(st + 10240 + so0,  Al + go0 + kq);
            cp16(st + 10240 + so1,  Al + go1 + kq);
            cp16(st + 20480 + so0,  Bh + go0 + kq);
            cp16(st + 20480 + so1,  Bh + go1 + kq);
            cp16(st + 30720 + so0,  Bl + go0 + kq);
            cp16(st + 30720 + so1,  Bl + go1 + kq);
            cp_commit();
        }

        const uint32_t st  = sb + (c & 1) * GSTG_B;
        #pragma unroll
        for (int kh = 0; kh < 2; kh++) {
            const uint32_t ko = kh * 32;           // 16 bf16 = 32 B
            const uint32_t stA  = st + ko,          stAl = st + 10240 + ko;
            const uint32_t stB  = st + 20480 + ko,  stBl = st + 30720 + ko;

            uint32_t ah[2][4], al[2][4];
            ldm4(ah[0], stA  + aoff0);
            ldm4(ah[1], stA  + aoff1);
            ldm4(al[0], stAl + aoff0);
            ldm4(al[1], stAl + aoff1);

            uint32_t bh[2][4], bl[2][4];
            ldm4(bh[0], stB  + boff[0]);
            ldm4(bl[0], stBl + boff[0]);
            #pragma unroll
            for (int p = 0; p < 4; p++) {
                const int cur = p & 1, nxt = cur ^ 1;
                if (p < 3) {
                    ldm4(bh[nxt], stB  + boff[p + 1]);
                    ldm4(bl[nxt], stBl + boff[p + 1]);
                }
                #pragma unroll
                for (int j = 0; j < 2; j++) {
                    const int nt = p * 2 + j;
                    #pragma unroll
                    for (int mt = 0; mt < 2; mt++) {
                        mma16(acc[mt][nt], al[mt], &bh[cur][2 * j]);
                        mma16(acc[mt][nt], ah[mt], &bl[cur][2 * j]);
                        mma16(acc[mt][nt], ah[mt], &bh[cur][2 * j]);
                    }
                }
            }
        }
    }
}

// QKV projection: scatter fp32 (tf32-rounded, Q pre-scaled) into [B,H,S,DH]
__global__ __launch_bounds__(256, 2) void gemm_qkv_tc() {
    extern __shared__ char smc[];
    const int z = blockIdx.z;
    float* Obuf = (z == 0) ? g_Q : (z == 1 ? g_K : g_V);
    const float scale = (z == 0) ? 0.125f : 1.0f;
    const int mBase = blockIdx.x * 128, nBase = blockIdx.y * 128;

    float acc[2][8][4];
    gemm_core_bf3(g_Xh + (size_t)mBase * Dd, g_Xl + (size_t)mBase * Dd,
                  g_Wh[z] + (size_t)nBase * Dd, g_Wl[z] + (size_t)nBase * Dd,
                  smc, acc);

    const int lane = threadIdx.x & 31, wid = threadIdx.x >> 5;
    const int wm = wid >> 1, wn = wid & 1;
    const int h = (nBase + wn * 64) >> 6;
    #pragma unroll
    for (int mt = 0; mt < 2; mt++) {
        int r0 = mBase + wm * 32 + mt * 16 + (lane >> 2);
        #pragma unroll
        for (int half = 0; half < 2; half++) {
            int row = r0 + half * 8;
            int bb = row >> 11, ssi = row & 2047;
            float* dst = Obuf + (((size_t)bb * Hh + h) * Ss + ssi) * DH;
            #pragma unroll
            for (int nt = 0; nt < 8; nt++) {
                int d = nt * 8 + 2 * (lane & 3);
                *(float2*)(dst + d) = make_float2(
                    to_tf32(acc[mt][nt][half * 2 + 0] * scale),
                    to_tf32(acc[mt][nt][half * 2 + 1] * scale));
            }
        }
    }
}

// output projection: fp32 store to d_out
__global__ __launch_bounds__(256, 2) void gemm_out_tc(float* __restrict__ C) {
    extern __shared__ char smc[];
    const int mBase = blockIdx.x * 128, nBase = blockIdx.y * 128;

    float acc[2][8][4];
    gemm_core_bf3(g_Oh + (size_t)mBase * Dd, g_Ol + (size_t)mBase * Dd,
                  g_Wh[3] + (size_t)nBase * Dd, g_Wl[3] + (size_t)nBase * Dd,
                  smc, acc);

    const int lane = threadIdx.x & 31, wid = threadIdx.x >> 5;
    const int wm = wid >> 1, wn = wid & 1;
    #pragma unroll
    for (int mt = 0; mt < 2; mt++) {
        int r0 = mBase + wm * 32 + mt * 16 + (lane >> 2);
        #pragma unroll
        for (int half = 0; half < 2; half++) {
            int row = r0 + half * 8;
            float* dst = C + (size_t)row * Dd + nBase + wn * 64;
            #pragma unroll
            for (int nt = 0; nt < 8; nt++) {
                int d = nt * 8 + 2 * (lane & 3);
                *(float2*)(dst + d) = make_float2(acc[mt][nt][half * 2 + 0],
                                                  acc[mt][nt][half * 2 + 1]);
            }
        }
    }
}

// ---------------- flash attention (unchanged) ----------------
#define QS_OFF 0
#define KS_OFF 8704
#define VS_OFF 13056
#define PS_OFF 17664

__global__ __launch_bounds__(128) void attn_mma() {
    extern __shared__ float sm[];
    float* Qs = sm + QS_OFF;
    float* Ks = sm + KS_OFF;
    float* Vs = sm + VS_OFF;
    float* Ps = sm + PS_OFF;

    const int tid = threadIdx.x;
    const int lane = tid & 31, wid = tid >> 5;
    const int qt = gridDim.x - 1 - blockIdx.x;
    const int h = blockIdx.y, b = blockIdx.z;

    const float* Qg = g_Q + (((size_t)b * Hh + h) * Ss + (size_t)qt * 128) * DH;
    const float* Kg = g_K + (((size_t)b * Hh + h) * Ss) * DH;
    const float* Vg = g_V + (((size_t)b * Hh + h) * Ss) * DH;

    uint32_t sQ = smem_u32(Qs), sK = smem_u32(Ks), sV = smem_u32(Vs);

    #pragma unroll
    for (int t = 0; t < 16; t++) {
        int idx = tid + t * 128;
        int r = idx >> 4, c = (idx & 15) * 4;
        cp16(sQ + (r * 68 + c) * 4, Qg + r * DH + c);
    }
    cp_commit();

    float o[2][8][4];
    float mrow[2][2], lrow[2][2];
    #pragma unroll
    for (int mt = 0; mt < 2; mt++) {
        mrow[mt][0] = mrow[mt][1] = -1e30f;
        lrow[mt][0] = lrow[mt][1] = 0.f;
        #pragma unroll
        for (int nt = 0; nt < 8; nt++)
            #pragma unroll
            for (int q = 0; q < 4; q++) o[mt][nt][q] = 0.f;
    }

    const int cL = lane & 3, rL = lane >> 2;
    const int ktMax = 2 * qt + 1;

    for (int kt = 0; kt <= ktMax; kt++) {
        __syncthreads();
        const float* Kp = Kg + (size_t)kt * 64 * DH;
        const float* Vp = Vg + (size_t)kt * 64 * DH;
        #pragma unroll
        for (int t = 0; t < 8; t++) {
            int idx = tid + t * 128;
            int r = idx >> 4, c = (idx & 15) * 4;
            cp16(sK + (r * 68 + c) * 4, Kp + r * DH + c);
            cp16(sV + (r * 72 + c) * 4, Vp + r * DH + c);
        }
        cp_commit();
        cp_wait0();
        __syncthreads();

        float s[2][8][4];
        #pragma unroll
        for (int mt = 0; mt < 2; mt++)
            #pragma unroll
            for (int nt = 0; nt < 8; nt++)
                #pragma unroll
                for (int q = 0; q < 4; q++) s[mt][nt][q] = 0.f;

        #pragma unroll
        for (int ks = 0; ks < 8; ks++) {
            const int kb = ks * 8 + cL;
            uint32_t bfr[8][2];
            #pragma unroll
            for (int nt = 0; nt < 8; nt++) {
                const float* kp = Ks + (nt * 8 + rL) * 68;
                bfr[nt][0] = f2u(kp[kb]);
                bfr[nt][1] = f2u(kp[kb + 4]);
            }
            #pragma unroll
            for (int mt = 0; mt < 2; mt++) {
                const float* qp = Qs + (wid * 32 + mt * 16 + rL) * 68;
                uint32_t a[4];
                a[0] = f2u(qp[kb]);
                a[1] = f2u(qp[8 * 68 + kb]);
                a[2] = f2u(qp[kb + 4]);
                a[3] = f2u(qp[8 * 68 + kb + 4]);
                #pragma unroll
                for (int nt = 0; nt < 8; nt++) mma8(s[mt][nt], a, bfr[nt]);
            }
        }

        if (kt >= 2 * qt) {
            #pragma unroll
            for (int mt = 0; mt < 2; mt++) {
                int rg0 = qt * 128 + wid * 32 + mt * 16 + rL;
                #pragma unroll
                for (int nt = 0; nt < 8; nt++) {
                    int cg = kt * 64 + nt * 8 + 2 * cL;
                    if (cg     > rg0)     s[mt][nt][0] = -1e30f;
                    if (cg + 1 > rg0)     s[mt][nt][1] = -1e30f;
                    if (cg     > rg0 + 8) s[mt][nt][2] = -1e30f;
                    if (cg + 1 > rg0 + 8) s[mt][nt][3] = -1e30f;
                }
            }
        }

        #pragma unroll
        for (int mt = 0; mt < 2; mt++) {
            float v0 = -1e30f, v1 = -1e30f;
            #pragma unroll
            for (int nt = 0; nt < 8; nt++) {
                v0 = fmaxf(v0, fmaxf(s[mt][nt][0], s[mt][nt][1]));
                v1 = fmaxf(v1, fmaxf(s[mt][nt][2], s[mt][nt][3]));
            }
            v0 = fmaxf(v0, __shfl_xor_sync(0xffffffffu, v0, 1));
            v0 = fmaxf(v0, __shfl_xor_sync(0xffffffffu, v0, 2));
            v1 = fmaxf(v1, __shfl_xor_sync(0xffffffffu, v1, 1));
            v1 = fmaxf(v1, __shfl_xor_sync(0xffffffffu, v1, 2));

            float mn0 = fmaxf(mrow[mt][0], v0);
            float mn1 = fmaxf(mrow[mt][1], v1);
            float cr0 = __expf(mrow[mt][0] - mn0);
            float cr1 = __expf(mrow[mt][1] - mn1);
            mrow[mt][0] = mn0; mrow[mt][1] = mn1;

            float rs0 = 0.f, rs1 = 0.f;
            float* prow0 = Ps + (wid * 32 + mt * 16 + rL) * 72;
            float* prow1 = prow0 + 8 * 72;
            #pragma unroll
            for (int nt = 0; nt < 8; nt++) {
                float p0 = __expf(s[mt][nt][0] - mn0);
                float p1 = __expf(s[mt][nt][1] - mn0);
                float p2 = __expf(s[mt][nt][2] - mn1);
                float p3 = __expf(s[mt][nt][3] - mn1);
                rs0 += p0 + p1; rs1 += p2 + p3;
                int cc = nt * 8 + 2 * cL;
                *(float2*)(prow0 + cc) = make_float2(to_tf32(p0), to_tf32(p1));
                *(float2*)(prow1 + cc) = make_float2(to_tf32(p2), to_tf32(p3));
            }
            rs0 += __shfl_xor_sync(0xffffffffu, rs0, 1);
            rs0 += __shfl_xor_sync(0xffffffffu, rs0, 2);
            rs1 += __shfl_xor_sync(0xffffffffu, rs1, 1);
            rs1 += __shfl_xor_sync(0xffffffffu, rs1, 2);
            lrow[mt][0] = lrow[mt][0] * cr0 + rs0;
            lrow[mt][1] = lrow[mt][1] * cr1 + rs1;
            #pragma unroll
            for (int nt = 0; nt < 8; nt++) {
                o[mt][nt][0] *= cr0; o[mt][nt][1] *= cr0;
                o[mt][nt][2] *= cr1; o[mt][nt][3] *= cr1;
            }
        }
        __syncwarp();

        #pragma unroll
        for (int ks = 0; ks < 8; ks++) {
            const int kb = ks * 8;
            uint32_t bfr[8][2];
            #pragma unroll
            for (int nt = 0; nt < 8; nt++) {
                bfr[nt][0] = f2u(Vs[(kb + cL) * 72 + nt * 8 + rL]);
                bfr[nt][1] = f2u(Vs[(kb + 4 + cL) * 72 + nt * 8 + rL]);
            }
            #pragma unroll
            for (int mt = 0; mt < 2; mt++) {
                const float* pp = Ps + (wid * 32 + mt * 16 + rL) * 72;
                uint32_t a[4];
                a[0] = f2u(pp[kb + cL]);
                a[1] = f2u(pp[8 * 72 + kb + cL]);
                a[2] = f2u(pp[kb + 4 + cL]);
                a[3] = f2u(pp[8 * 72 + kb + 4 + cL]);
                #pragma unroll
                for (int nt = 0; nt < 8; nt++) mma8(o[mt][nt], a, bfr[nt]);
            }
        }
    }

    #pragma unroll
    for (int mt = 0; mt < 2; mt++) {
        float inv0 = 1.f / lrow[mt][0];
        float inv1 = 1.f / lrow[mt][1];
        int r0 = qt * 128 + wid * 32 + mt * 16 + rL;
        size_t base0 = ((size_t)b * Ss + r0) * Dd + h * DH;
        size_t base1 = base0 + 8 * Dd;
        #pragma unroll
        for (int nt = 0; nt < 8; nt++) {
            int cc = nt * 8 + 2 * cL;
            float x0 = o[mt][nt][0] * inv0, x1 = o[mt][nt][1] * inv0;
            float x2 = o[mt][nt][2] * inv1, x3 = o[mt][nt][3] * inv1;
            __nv_bfloat16 h0, l0, h1, l1, h2, l2, h3, l3;
            decb(x0, h0, l0); decb(x1, h1, l1);
            decb(x2, h2, l2); decb(x3, h3, l3);
            *(__nv_bfloat162*)(g_Oh + base0 + cc) = __nv_bfloat162(h0, h1);
            *(__nv_bfloat162*)(g_Ol + base0 + cc) = __nv_bfloat162(l0, l1);
            *(__nv_bfloat162*)(g_Oh + base1 + cc) = __nv_bfloat162(h2, h3);
            *(__nv_bfloat162*)(g_Ol + base1 + cc) = __nv_bfloat162(l2, l3);
        }
    }
}

// ---------------------------------------------------------------------------

extern "C" void kernel_launch(void* const* d_in, const int* in_sizes, int n_in,
                              void* d_out, int out_size)
{
    const float* x  = (const float*)d_in[0];
    const float* Wq = (const float*)d_in[1];
    const float* Wk = (const float*)d_in[2];
    const float* Wv = (const float*)d_in[3];
    const float* Wo = (const float*)d_in[4];
    float* out = (float*)d_out;

    const int GEMM_SMEM = 2 * GSTG_B;                          // 81920
    const int ATTN_SMEM = (PS_OFF + 128 * 72) * (int)sizeof(float);

    cudaFuncSetAttribute(gemm_qkv_tc, cudaFuncAttributeMaxDynamicSharedMemorySize, GEMM_SMEM);
    cudaFuncSetAttribute(gemm_out_tc, cudaFuncAttributeMaxDynamicSharedMemorySize, GEMM_SMEM);
    cudaFuncSetAttribute(attn_mma,    cudaFuncAttributeMaxDynamicSharedMemorySize, ATTN_SMEM);

    conv_all<<<512, 256>>>(x, Wq, Wk, Wv, Wo);
    gemm_qkv_tc<<<dim3(Mm / 128, Dd / 128, 3), 256, GEMM_SMEM>>>();
    attn_mma<<<dim3(Ss / 128, Hh, Bb), 128, ATTN_SMEM>>>();
    gemm_out_tc<<<dim3(Mm / 128, Dd / 128), 256, GEMM_SMEM>>>(out);
}